// round 4
// baseline (speedup 1.0000x reference)
#include <cuda_runtime.h>

// Problem dims
#define N_  20000
#define K_  20
#define T_  50
#define D_  200
#define T2  25            // t-pairs (f32x2 packing over fastest axis)
#define NT  32            // n rows per block
#define DC  5             // d chunk size
#define NNN 4             // n rows per compute thread
#define GRP (NT/NNN)      // 8
#define CTH (GRP*T2)      // 200 compute threads per group
#define GBLK 256          // threads per d-group
#define NGROUP 4
#define BLK  (GBLK*NGROUP) // 1024
#define CPG  10           // chunks per group (D/DC/NGROUP = 200/5/4)
#define EPSF 1e-8f

typedef unsigned long long u64;

// Precomputed sigmoid(phi), filled by kernel 1, read by kernel 2.
__device__ float g_phiprob[K_ * D_ * T_];

__device__ __forceinline__ u64 ffma2(u64 a, u64 b, u64 c) {
    u64 d;
    asm("fma.rn.f32x2 %0, %1, %2, %3;" : "=l"(d) : "l"(a), "l"(b), "l"(c));
    return d;
}

__device__ __forceinline__ void group_bar(int bar_id) {
    asm volatile("bar.sync %0, %1;" :: "r"(bar_id), "r"(GBLK) : "memory");
}

__global__ void phi_sigmoid_kernel(const float* __restrict__ phi,
                                   float* __restrict__ out_phi) {
    int i = blockIdx.x * blockDim.x + threadIdx.x;
    if (i < K_ * D_ * T_) {
        float p = __fdividef(1.f, 1.f + __expf(-phi[i]));
        out_phi[i]   = p;
        g_phiprob[i] = p;
    }
}

__global__ __launch_bounds__(BLK, 1) void main_kernel(
    const float* __restrict__ lambda_,
    float* __restrict__ pi_out,
    float* __restrict__ theta_out)
{
    extern __shared__ float2 smem[];
    float2* theta_s = smem;                      // [K_][NT][T2]          = 128000 B
    float2* phi_all = smem + K_ * NT * T2;       // NGROUP x [K_][DC][T2] =  80000 B

    const int tid   = threadIdx.x;
    const int nbase = blockIdx.x * NT;
    const float2* lam2 = (const float2*)lambda_;
    float2*       th2  = (float2*)theta_out;
    float2*       pi2  = (float2*)pi_out;
    const float2* pp2  = (const float2*)g_phiprob;

    // ---------------- Stage 1: softmax over K for this block's 32 n's ----------------
    if (tid < NT * T2) {                         // 800 of 1024 threads, one cell each
        int t2 = tid % T2;
        int n  = tid / T2;
        size_t base = (size_t)(nbase + n) * K_ * T2 + t2;

        float2 v[K_];
        #pragma unroll
        for (int k = 0; k < K_; k++) v[k] = lam2[base + (size_t)k * T2];

        float mx = v[0].x, my = v[0].y;
        #pragma unroll
        for (int k = 1; k < K_; k++) { mx = fmaxf(mx, v[k].x); my = fmaxf(my, v[k].y); }

        float sx = 0.f, sy = 0.f;
        #pragma unroll
        for (int k = 0; k < K_; k++) {
            v[k].x = __expf(v[k].x - mx);
            v[k].y = __expf(v[k].y - my);
            sx += v[k].x; sy += v[k].y;
        }
        float ix = __fdividef(1.f, sx), iy = __fdividef(1.f, sy);

        #pragma unroll
        for (int k = 0; k < K_; k++) {
            float2 th; th.x = v[k].x * ix; th.y = v[k].y * iy;
            theta_s[(k * NT + n) * T2 + t2] = th;       // [k][n][t2]
            th2[base + (size_t)k * T2] = th;            // coalesced global write
        }
    }
    __syncthreads();

    // ---------------- Stage 2: four independent 256-thread d-groups ----------------
    const int gsel = tid / GBLK;            // 0..3 (warp-aligned)
    const int ltid = tid % GBLK;
    float2* phi_s  = phi_all + gsel * (K_ * DC * T2);
    const int bar  = 1 + gsel;

    const int t2c = ltid % T2;
    const int g   = ltid / T2;              // 0..7 compute, 8..10 idle lanes
    const int n0  = g * NNN;

    for (int c = 0; c < CPG; c++) {
        const int d0 = (gsel * CPG + c) * DC;

        // Stage phi_prob chunk [K_][DC][T2]: 2500 f32x2, linear copy
        {
            const float2* src_base = pp2 + (size_t)d0 * T2;
            #pragma unroll 1
            for (int i = ltid; i < K_ * DC * T2; i += GBLK) {
                int k   = i / (DC * T2);
                int rem = i - k * (DC * T2);
                phi_s[i] = src_base[(size_t)k * (D_ * T2) + rem];
            }
        }
        group_bar(bar);

        if (ltid < CTH) {
            u64 acc[NNN][DC];
            #pragma unroll
            for (int i = 0; i < NNN; i++)
                #pragma unroll
                for (int d = 0; d < DC; d++) acc[i][d] = 0ull;

            #pragma unroll
            for (int k = 0; k < K_; k++) {
                u64 th[NNN], ph[DC];
                #pragma unroll
                for (int i = 0; i < NNN; i++)
                    th[i] = *(const u64*)&theta_s[(k * NT + n0 + i) * T2 + t2c];
                #pragma unroll
                for (int d = 0; d < DC; d++)
                    ph[d] = *(const u64*)&phi_s[(k * DC + d) * T2 + t2c];
                #pragma unroll
                for (int i = 0; i < NNN; i++)
                    #pragma unroll
                    for (int d = 0; d < DC; d++)
                        acc[i][d] = ffma2(th[i], ph[d], acc[i][d]);
            }

            float2* pi_base = pi2 + ((size_t)(nbase + n0) * D_ + d0) * T2 + t2c;
            #pragma unroll
            for (int i = 0; i < NNN; i++) {
                #pragma unroll
                for (int d = 0; d < DC; d++) {
                    float2 f;
                    asm("mov.b64 {%0, %1}, %2;" : "=f"(f.x), "=f"(f.y) : "l"(acc[i][d]));
                    f.x = fminf(fmaxf(f.x, EPSF), 1.f - EPSF);
                    f.y = fminf(fmaxf(f.y, EPSF), 1.f - EPSF);
                    pi_base[((size_t)i * D_ + d) * T2] = f;
                }
            }
        }
        group_bar(bar);   // protect phi_s before next chunk's staging
    }
}

extern "C" void kernel_launch(void* const* d_in, const int* in_sizes, int n_in,
                              void* d_out, int out_size) {
    const float* lambda_ = (const float*)d_in[0];   // [N, K, T]
    const float* phi     = (const float*)d_in[1];   // [K, D, T]

    float* out         = (float*)d_out;
    float* pi_out      = out;                                // 200,000,000
    float* theta_out   = out + (size_t)N_ * D_ * T_;         //  20,000,000
    float* phiprob_out = theta_out + (size_t)N_ * K_ * T_;   //     200,000

    phi_sigmoid_kernel<<<(K_ * D_ * T_ + 255) / 256, 256>>>(phi, phiprob_out);

    size_t smem_bytes = sizeof(float2) *
        (size_t)(K_ * NT * T2 + NGROUP * K_ * DC * T2);      // 208000 B
    cudaFuncSetAttribute(main_kernel, cudaFuncAttributeMaxDynamicSharedMemorySize,
                         (int)smem_bytes);
    main_kernel<<<N_ / NT, BLK, smem_bytes>>>(lambda_, pi_out, theta_out);
}